// round 11
// baseline (speedup 1.0000x reference)
#include <cuda_runtime.h>
#include <math.h>

typedef unsigned long long ull;

// ---------------- static scratch (no runtime allocation allowed) ----------------
#define MAXN 100000
#define MAXNODES 1000000

__device__ int   g_assoc[MAXNODES];
__device__ float g_Q   [(size_t)MAXN*100];
__device__ float g_K   [(size_t)MAXN*100];
__device__ float g_V   [(size_t)MAXN*100];
__device__ float g_AGG [(size_t)MAXN*100];   // skip projection (z @ Wskip^T + b)
__device__ float g_AGGW[(size_t)MAXN*100];   // unnormalized attention aggregation
__device__ float g_aden[(size_t)MAXN*2];     // softmax denominators per (node, head)

// ---------------- f32x2 packed-FMA helpers (full-rate FFMA on sm_103a) ----------
__device__ __forceinline__ ull pack2(float x, float y) {
    ull r; asm("mov.b64 %0,{%1,%2};" : "=l"(r) : "f"(x), "f"(y)); return r;
}
__device__ __forceinline__ float2 unpack2(ull v) {
    float2 r; asm("mov.b64 {%0,%1},%2;" : "=f"(r.x), "=f"(r.y) : "l"(v)); return r;
}
__device__ __forceinline__ void ffma2(ull& d, ull a, ull b) {
    asm("fma.rn.f32x2 %0,%1,%2,%3;" : "=l"(d) : "l"(a), "l"(b), "l"(d));
}

// ---------------- init: AGGW = 0, aden = 0 ---------------------------------------
__global__ void init_kernel(int N) {
    int i = blockIdx.x * blockDim.x + threadIdx.x;
    if (i < N * 25) ((float4*)g_AGGW)[i] = make_float4(0.f, 0.f, 0.f, 0.f);
    if (i < 2 * N) g_aden[i] = 0.f;
}

__global__ void assoc_kernel(const int* __restrict__ n_id, int N) {
    int i = blockIdx.x * blockDim.x + threadIdx.x;
    if (i < N) g_assoc[n_id[i]] = i;
}

// =================================================================================
// Geometry: BM=128, BN=100, TPB=320 (10 warps -> SMSP 3,3,2,2 balanced).
// Each warp = 16 units (lane pairs); unit = (rg, cg) with TM=8, TN=10.
// Lane parity ks splits K in half; acc reduced by __shfl_xor(1) at the end.
// A panel k-major a_s[k*SA+r]; B panel k-major b_s[k*100+c]. Full-K staging,
// 1 CTA/SM (smem ~95KB), reg cap 204 -> no spills.
// =================================================================================
#define TPB 320
#define SA  132

// ---------------- fused Q/K/V/skip GEMM: C = z @ W^T + b -------------------------
__global__ void __launch_bounds__(TPB, 1) qkvs_kernel(
    const float* __restrict__ z,
    const float* __restrict__ W0, const float* __restrict__ b0,
    const float* __restrict__ W1, const float* __restrict__ b1,
    const float* __restrict__ W2, const float* __restrict__ b2v,
    const float* __restrict__ W3, const float* __restrict__ b3,
    int N, int ntiles)
{
    extern __shared__ float sm[];
    float* b_s    = sm;                  // [100][100] k-major (W^T)
    float* a_s    = sm + 10000;          // [100][132] k-major, full K
    float* bias_s = a_s + 100 * SA;      // [100]

    const float* W; const float* bias; float* out;
    switch (blockIdx.y) {
        case 0:  W = W0; bias = b0;  out = g_Q;   break;
        case 1:  W = W1; bias = b1;  out = g_K;   break;
        case 2:  W = W2; bias = b2v; out = g_V;   break;
        default: W = W3; bias = b3;  out = g_AGG; break;
    }
    int tid = threadIdx.x;

    for (int idx = tid; idx < 10000; idx += TPB) {
        int o = idx / 100, k = idx - o * 100;
        b_s[k * 100 + o] = W[idx];
    }
    if (tid < 100) bias_s[tid] = bias[tid];

    int lane = tid & 31, w = tid >> 5;
    int unit = w * 16 + (lane >> 1);
    int ks   = lane & 1;                 // K-half of this lane
    int rg = unit / 10, cg = unit % 10;
    int rb = rg * 8, cb = cg * 10;
    int kbase = ks * 50;

    for (int tile = blockIdx.x; tile < ntiles; tile += gridDim.x) {
        int row0 = tile * 128;
        __syncthreads();                 // prev tile readers done
        for (int idx = tid; idx < 6400; idx += TPB) {
            int r = idx / 50, k2 = idx - r * 50;
            int gr = row0 + r;
            float2 v = make_float2(0.f, 0.f);
            if (gr < N) v = *(const float2*)(z + (size_t)gr * 100 + 2 * k2);
            a_s[(2 * k2) * SA + r]     = v.x;
            a_s[(2 * k2 + 1) * SA + r] = v.y;
        }
        __syncthreads();

        ull acc[8][5];
        #pragma unroll
        for (int i = 0; i < 8; i++)
            #pragma unroll
            for (int j = 0; j < 5; j++) acc[i][j] = 0ull;

        #pragma unroll 2
        for (int kk = 0; kk < 50; kk++) {
            int k = kbase + kk;
            const float* ar = a_s + k * SA;
            float4 a0 = *(const float4*)(ar + rb);
            float4 a1 = *(const float4*)(ar + rb + 4);
            const ull* bp = (const ull*)(b_s + k * 100 + cb);
            ull b2[5];
            #pragma unroll
            for (int j = 0; j < 5; j++) b2[j] = bp[j];
            ull av[8] = { pack2(a0.x, a0.x), pack2(a0.y, a0.y),
                          pack2(a0.z, a0.z), pack2(a0.w, a0.w),
                          pack2(a1.x, a1.x), pack2(a1.y, a1.y),
                          pack2(a1.z, a1.z), pack2(a1.w, a1.w) };
            #pragma unroll
            for (int i = 0; i < 8; i++)
                #pragma unroll
                for (int j = 0; j < 5; j++) ffma2(acc[i][j], av[i], b2[j]);
        }

        // ---- reduce K halves across lane pairs ----
        #pragma unroll
        for (int i = 0; i < 8; i++)
            #pragma unroll
            for (int j = 0; j < 5; j++) {
                ull o = __shfl_xor_sync(0xffffffffu, acc[i][j], 1);
                float2 a = unpack2(acc[i][j]), b = unpack2(o);
                acc[i][j] = pack2(a.x + b.x, a.y + b.y);
            }

        // ---- write: even lane rows 0-3, odd lane rows 4-7 ----
        #pragma unroll
        for (int i = 0; i < 8; i++) {
            if ((i >> 2) == ks) {
                int gr = row0 + rb + i;
                if (gr < N) {
                    float2* op = (float2*)(out + (size_t)gr * 100 + cb);
                    #pragma unroll
                    for (int j = 0; j < 5; j++) {
                        float2 r = unpack2(acc[i][j]);
                        r.x += bias_s[cb + 2 * j];
                        r.y += bias_s[cb + 2 * j + 1];
                        op[j] = r;
                    }
                }
            }
        }
    }
}

// =================================================================================
// fused edge kernel: e_proj GEMM (attr generated in smem via __cosf) + alpha +
// max-free softmax weight + weighted scatter. K=101: ks=0 -> [0,50), ks=1 -> [50,101).
// =================================================================================
__global__ void __launch_bounds__(TPB, 1) edge_kernel(
    const float* __restrict__ lu, const float* __restrict__ t,
    const float* __restrict__ msg,
    const float* __restrict__ tw, const float* __restrict__ tb,
    const float* __restrict__ We, const int* __restrict__ ei,
    int E, int ntiles)
{
    extern __shared__ float sm[];
    float* b_s   = sm;                      // [101][100] k-major (We^T)
    float* a_s   = b_s + 10100;             // [101][132] generated attr, full K
    float* tw_s  = a_s + 101 * SA;          // [100]
    float* tb_s  = tw_s + 100;              // [100]
    float* rel_s = tb_s + 100;              // [128]
    float* msg_s = rel_s + 128;             // [128]
    float* apart = msg_s + 128;             // [256] alpha partials, then w
    int*   sidx  = (int*)(apart + 256);     // [128]
    int*   didx  = sidx + 128;              // [128]

    int tid = threadIdx.x;
    for (int idx = tid; idx < 10100; idx += TPB) {
        int o = idx / 101, k = idx - o * 101;
        b_s[k * 100 + o] = We[idx];
    }
    if (tid < 100) { tw_s[tid] = tw[tid]; tb_s[tid] = tb[tid]; }

    int lane = tid & 31, w = tid >> 5;
    int unit = w * 16 + (lane >> 1);
    int ks   = lane & 1;
    int rg = unit / 10, cg = unit % 10;
    int rb = rg * 8, cb = cg * 10;
    int h  = (cg >= 5) ? 1 : 0;             // head of this colgroup
    int kbase = ks * 50;
    const float inv = 0.14142135623730951f; // 1/sqrt(50)

    for (int tile = blockIdx.x; tile < ntiles; tile += gridDim.x) {
        int e0 = tile * 128;
        __syncthreads();                     // prev tile fully consumed
        if (tid < 128) {
            int e = e0 + tid; float rv = 0.f, mv = 0.f; int s = 0, d = 0;
            if (e < E) { s = ei[e]; d = ei[E + e]; rv = lu[s] - t[e]; mv = msg[e]; }
            rel_s[tid] = rv; msg_s[tid] = mv; sidx[tid] = s; didx[tid] = d;
        }
        if (tid < 256) apart[tid] = 0.f;
        __syncthreads();                     // rel/msg ready

        // generate full attr panel: k<100 -> cos, k==100 -> msg
        for (int idx = tid; idx < 101 * 128; idx += TPB) {
            int kk = idx >> 7, r = idx & 127;
            a_s[kk * SA + r] =
                (kk < 100) ? __cosf(fmaf(rel_s[r], tw_s[kk], tb_s[kk])) : msg_s[r];
        }
        __syncthreads();                     // a_s ready

        ull acc[8][5];
        #pragma unroll
        for (int i = 0; i < 8; i++)
            #pragma unroll
            for (int j = 0; j < 5; j++) acc[i][j] = 0ull;

        #pragma unroll 2
        for (int kk = 0; kk < 50; kk++) {
            int k = kbase + kk;
            const float* ar = a_s + k * SA;
            float4 a0 = *(const float4*)(ar + rb);
            float4 a1 = *(const float4*)(ar + rb + 4);
            const ull* bp = (const ull*)(b_s + k * 100 + cb);
            ull b2[5];
            #pragma unroll
            for (int j = 0; j < 5; j++) b2[j] = bp[j];
            ull av[8] = { pack2(a0.x, a0.x), pack2(a0.y, a0.y),
                          pack2(a0.z, a0.z), pack2(a0.w, a0.w),
                          pack2(a1.x, a1.x), pack2(a1.y, a1.y),
                          pack2(a1.z, a1.z), pack2(a1.w, a1.w) };
            #pragma unroll
            for (int i = 0; i < 8; i++)
                #pragma unroll
                for (int j = 0; j < 5; j++) ffma2(acc[i][j], av[i], b2[j]);
        }
        if (ks) {                            // tail k = 100 (msg row), odd lanes
            const float* ar = a_s + 100 * SA;
            float4 a0 = *(const float4*)(ar + rb);
            float4 a1 = *(const float4*)(ar + rb + 4);
            const ull* bp = (const ull*)(b_s + 100 * 100 + cb);
            ull b2[5];
            #pragma unroll
            for (int j = 0; j < 5; j++) b2[j] = bp[j];
            ull av[8] = { pack2(a0.x, a0.x), pack2(a0.y, a0.y),
                          pack2(a0.z, a0.z), pack2(a0.w, a0.w),
                          pack2(a1.x, a1.x), pack2(a1.y, a1.y),
                          pack2(a1.z, a1.z), pack2(a1.w, a1.w) };
            #pragma unroll
            for (int i = 0; i < 8; i++)
                #pragma unroll
                for (int j = 0; j < 5; j++) ffma2(acc[i][j], av[i], b2[j]);
        }

        // ---- reduce K halves across lane pairs ----
        #pragma unroll
        for (int i = 0; i < 8; i++)
            #pragma unroll
            for (int j = 0; j < 5; j++) {
                ull o = __shfl_xor_sync(0xffffffffu, acc[i][j], 1);
                float2 a = unpack2(acc[i][j]), b = unpack2(o);
                acc[i][j] = pack2(a.x + b.x, a.y + b.y);
            }

        // ---- alpha partials: even lane rows 0-3, odd rows 4-7 ----
        #pragma unroll
        for (int i = 0; i < 8; i++) {
            if ((i >> 2) == ks) {
                int r = rb + i, e = e0 + r;
                if (e < E) {
                    int s = sidx[r], d = didx[r];
                    const float2* qp = (const float2*)(g_Q + (size_t)d * 100 + cb);
                    const float2* kp = (const float2*)(g_K + (size_t)s * 100 + cb);
                    float part = 0.f;
                    #pragma unroll
                    for (int j = 0; j < 5; j++) {
                        float2 ep = unpack2(acc[i][j]);
                        float2 qv = qp[j];
                        float2 kv = kp[j];
                        part = fmaf(qv.x, kv.x + ep.x, part);
                        part = fmaf(qv.y, kv.y + ep.y, part);
                    }
                    atomicAdd(&apart[2 * r + h], part);
                }
            }
        }
        __syncthreads();                     // apart complete

        // ---- w = exp(alpha) (max-free), accumulate denominators ----
        if (tid < 256) {
            int r = tid >> 1, hh = tid & 1;
            int e = e0 + r;
            if (e < E) {
                float ww = __expf(apart[tid] * inv);
                apart[tid] = ww;             // reuse as w_s
                atomicAdd(&g_aden[2 * didx[r] + hh], ww);
            }
        }
        __syncthreads();                     // w ready

        // ---- scatter: AGGW[dst] += (v[src] + e_proj) * w  (vector REDs) ----
        #pragma unroll
        for (int i = 0; i < 8; i++) {
            if ((i >> 2) == ks) {
                int r = rb + i, e = e0 + r;
                if (e < E) {
                    int s = sidx[r], d = didx[r];
                    const float2* vp = (const float2*)(g_V + (size_t)s * 100 + cb);
                    float ww = apart[2 * r + h];
                    float m[10];
                    #pragma unroll
                    for (int j = 0; j < 5; j++) {
                        float2 ep = unpack2(acc[i][j]);
                        float2 vv = vp[j];
                        m[2 * j]     = (vv.x + ep.x) * ww;
                        m[2 * j + 1] = (vv.y + ep.y) * ww;
                    }
                    float* op = g_AGGW + (size_t)d * 100 + cb;
                    if ((cg & 1) == 0) {   // cb % 4 == 0 : 4+4+2
                        atomicAdd((float4*)op,       make_float4(m[0], m[1], m[2], m[3]));
                        atomicAdd((float4*)(op + 4), make_float4(m[4], m[5], m[6], m[7]));
                        atomicAdd((float2*)(op + 8), make_float2(m[8], m[9]));
                    } else {               // cb % 4 == 2 : 2+4+4
                        atomicAdd((float2*)op,       make_float2(m[0], m[1]));
                        atomicAdd((float4*)(op + 2), make_float4(m[2], m[3], m[4], m[5]));
                        atomicAdd((float4*)(op + 6), make_float4(m[6], m[7], m[8], m[9]));
                    }
                }
            }
        }
    }
}

// =================================================================================
// link predictor with fused normalization:
// z_out = AGG(skip) + AGGW/aden ; out = relu(z_s@Ws^T + z_d@Wd^T + b) @ Wf^T + bf
// =================================================================================
__global__ void __launch_bounds__(128) linkpred_kernel(
    const float* __restrict__ Wsrc, const float* __restrict__ bsrc,
    const float* __restrict__ Wdst, const float* __restrict__ bdst,
    const float* __restrict__ Wf,   const float* __restrict__ bf,
    const int* __restrict__ src, const int* __restrict__ dst,
    float* __restrict__ out, int B)
{
    extern __shared__ float sm[];
    float* Ws   = sm;                 // [100][101] padded
    float* Wd   = Ws + 100 * 101;
    float* bsum = Wd + 100 * 101;
    float* wf   = bsum + 100;
    float* zrow = wf + 100;           // 4 warps * 200

    int tid = threadIdx.x, lane = tid & 31, warp = tid >> 5;
    for (int idx = tid; idx < 10000; idx += 128) {
        int o = idx / 100, k = idx - o * 100;
        Ws[o * 101 + k] = Wsrc[idx];
        Wd[o * 101 + k] = Wdst[idx];
    }
    if (tid < 100) { bsum[tid] = bsrc[tid] + bdst[tid]; wf[tid] = Wf[tid]; }
    __syncthreads();

    float bf0 = bf[0];
    float* zs = zrow + warp * 200;
    float* zd = zs + 100;

    for (int p = blockIdx.x * 4 + warp; p < B; p += gridDim.x * 4) {
        int sp = g_assoc[src[p]];
        int dp = g_assoc[dst[p]];
        float ds0 = g_aden[2 * sp], ds1 = g_aden[2 * sp + 1];
        float dd0 = g_aden[2 * dp], dd1 = g_aden[2 * dp + 1];
        float is0 = ds0 > 0.f ? 1.f / ds0 : 0.f;
        float is1 = ds1 > 0.f ? 1.f / ds1 : 0.f;
        float id0 = dd0 > 0.f ? 1.f / dd0 : 0.f;
        float id1 = dd1 > 0.f ? 1.f / dd1 : 0.f;
        for (int c = lane; c < 100; c += 32) {
            float invs = (c < 50) ? is0 : is1;
            float invd = (c < 50) ? id0 : id1;
            zs[c] = fmaf(g_AGGW[(size_t)sp * 100 + c], invs, g_AGG[(size_t)sp * 100 + c]);
            zd[c] = fmaf(g_AGGW[(size_t)dp * 100 + c], invd, g_AGG[(size_t)dp * 100 + c]);
        }
        __syncwarp();
        float acc = 0.f;
        for (int o = lane; o < 100; o += 32) {
            float hh = bsum[o];
            const float* wsr = Ws + o * 101;
            const float* wdr = Wd + o * 101;
            #pragma unroll 10
            for (int k = 0; k < 100; k++) {
                hh = fmaf(wsr[k], zs[k], hh);
                hh = fmaf(wdr[k], zd[k], hh);
            }
            hh = fmaxf(hh, 0.f);
            acc = fmaf(hh, wf[o], acc);
        }
        #pragma unroll
        for (int o = 16; o; o >>= 1) acc += __shfl_xor_sync(0xffffffffu, acc, o);
        if (lane == 0) out[p] = acc + bf0;
        __syncwarp();
    }
}

// ---------------- launch ----------------------------------------------------------
extern "C" void kernel_launch(void* const* d_in, const int* in_sizes, int n_in,
                              void* d_out, int out_size)
{
    const float* z     = (const float*)d_in[0];
    const float* lu    = (const float*)d_in[1];
    const float* t     = (const float*)d_in[2];
    const float* msg   = (const float*)d_in[3];
    const float* tw    = (const float*)d_in[4];
    const float* tb    = (const float*)d_in[5];
    const float* Wq    = (const float*)d_in[6];
    const float* bq    = (const float*)d_in[7];
    const float* Wk    = (const float*)d_in[8];
    const float* bk    = (const float*)d_in[9];
    const float* Wv    = (const float*)d_in[10];
    const float* bv    = (const float*)d_in[11];
    const float* We    = (const float*)d_in[12];
    const float* Wskip = (const float*)d_in[13];
    const float* bskip = (const float*)d_in[14];
    const float* Wsrc  = (const float*)d_in[15];
    const float* bsrc  = (const float*)d_in[16];
    const float* Wdst  = (const float*)d_in[17];
    const float* bdst  = (const float*)d_in[18];
    const float* Wf    = (const float*)d_in[19];
    const float* bf    = (const float*)d_in[20];
    const int*   n_id  = (const int*)d_in[21];
    const int*   srcp  = (const int*)d_in[22];
    const int*   dstp  = (const int*)d_in[23];
    const int*   ei    = (const int*)d_in[24];

    int N = in_sizes[0] / 100;
    int E = in_sizes[2];
    int B = in_sizes[22];
    float* out = (float*)d_out;

    int ntilesN = (N + 127) / 128;
    int ntilesE = (E + 127) / 128;

    const int SMEM_QKVS = (10000 + 100 * SA + 100) * 4;                        // ~93.2 KB
    const int SMEM_EDGE = (10100 + 101 * SA + 100 + 100 + 128 + 128 + 256
                           + 128 + 128) * 4;                                   // ~97.6 KB
    const int SMEM_LP   = (2 * 100 * 101 + 200 + 4 * 200) * 4;                 // ~84.8 KB

    cudaFuncSetAttribute(qkvs_kernel,     cudaFuncAttributeMaxDynamicSharedMemorySize, SMEM_QKVS);
    cudaFuncSetAttribute(edge_kernel,     cudaFuncAttributeMaxDynamicSharedMemorySize, SMEM_EDGE);
    cudaFuncSetAttribute(linkpred_kernel, cudaFuncAttributeMaxDynamicSharedMemorySize, SMEM_LP);

    init_kernel<<<(N * 25 + 255) / 256, 256>>>(N);
    assoc_kernel<<<(N + 255) / 256, 256>>>(n_id, N);

    dim3 gq(37, 4);    // 148 persistent CTAs (1/SM), 4 weight sets
    qkvs_kernel<<<gq, TPB, SMEM_QKVS>>>(z, Wq, bq, Wk, bk, Wv, bv, Wskip, bskip,
                                        N, ntilesN);

    edge_kernel<<<148, TPB, SMEM_EDGE>>>(lu, t, msg, tw, tb, We, ei, E, ntilesE);

    linkpred_kernel<<<296, 128, SMEM_LP>>>(Wsrc, bsrc, Wdst, bdst, Wf, bf,
                                           srcp, dstp, out, B);
}

// round 12
// speedup vs baseline: 1.3522x; 1.3522x over previous
#include <cuda_runtime.h>
#include <math.h>

typedef unsigned long long ull;

// ---------------- static scratch (no runtime allocation allowed) ----------------
#define MAXN 100000
#define MAXNODES 1000000

__device__ int   g_assoc[MAXNODES];
__device__ float g_Q   [(size_t)MAXN*100];
__device__ float g_K   [(size_t)MAXN*100];
__device__ float g_V   [(size_t)MAXN*100];
__device__ float g_AGG [(size_t)MAXN*100];   // skip projection (z @ Wskip^T + b)
__device__ float g_AGGW[(size_t)MAXN*100];   // unnormalized attention aggregation
__device__ float g_aden[(size_t)MAXN*2];     // softmax denominators per (node, head)

// ---------------- f32x2 packed-FMA helpers (full-rate FFMA on sm_103a) ----------
__device__ __forceinline__ ull pack2(float x, float y) {
    ull r; asm("mov.b64 %0,{%1,%2};" : "=l"(r) : "f"(x), "f"(y)); return r;
}
__device__ __forceinline__ float2 unpack2(ull v) {
    float2 r; asm("mov.b64 {%0,%1},%2;" : "=f"(r.x), "=f"(r.y) : "l"(v)); return r;
}
__device__ __forceinline__ void ffma2(ull& d, ull a, ull b) {
    asm("fma.rn.f32x2 %0,%1,%2,%3;" : "=l"(d) : "l"(a), "l"(b), "l"(d));
}

// ---------------- init: AGGW = 0, aden = 0 ---------------------------------------
__global__ void init_kernel(int N) {
    int i = blockIdx.x * blockDim.x + threadIdx.x;
    if (i < N * 25) ((float4*)g_AGGW)[i] = make_float4(0.f, 0.f, 0.f, 0.f);
    if (i < 2 * N) g_aden[i] = 0.f;
}

__global__ void assoc_kernel(const int* __restrict__ n_id, int N) {
    int i = blockIdx.x * blockDim.x + threadIdx.x;
    if (i < N) g_assoc[n_id[i]] = i;
}

// =================================================================================
// Geometry: BM=192 (two 96-row sub-tiles), BN=100, TPB=320.
// Warps 0-4 -> sub-tile 0 (rows 0-95), warps 5-9 -> sub-tile 1 (rows 96-191).
// Per-thread: TM=6 x TN=10 (acc = 30 ull = 60 regs -> ~100 regs, no spills,
// 2 CTAs/SM = 20 warps, SMSP 3,3,2,2 balance). A k-major a_s[k*SAR + r], SAR=196.
// =================================================================================
#define TPB 320
#define SAR 196

// ---------------- fused Q/K/V/skip GEMM: C = z @ W^T + b -------------------------
__global__ void __launch_bounds__(TPB, 2) qkvs_kernel(
    const float* __restrict__ z,
    const float* __restrict__ W0, const float* __restrict__ b0,
    const float* __restrict__ W1, const float* __restrict__ b1,
    const float* __restrict__ W2, const float* __restrict__ b2v,
    const float* __restrict__ W3, const float* __restrict__ b3,
    int N, int ntiles)
{
    extern __shared__ float sm[];
    float* b_s    = sm;                  // [100][100] k-major (W^T)
    float* a_s    = sm + 10000;          // [50][196] k-major tile (192 rows + pad)
    float* bias_s = a_s + 50 * SAR;      // [100]

    const float* W; const float* bias; float* out;
    switch (blockIdx.y) {
        case 0:  W = W0; bias = b0;  out = g_Q;   break;
        case 1:  W = W1; bias = b1;  out = g_K;   break;
        case 2:  W = W2; bias = b2v; out = g_V;   break;
        default: W = W3; bias = b3;  out = g_AGG; break;
    }
    int tid = threadIdx.x;

    for (int idx = tid; idx < 10000; idx += TPB) {
        int o = idx / 100, k = idx - o * 100;
        b_s[k * 100 + o] = W[idx];
    }
    if (tid < 100) bias_s[tid] = bias[tid];

    int w = tid >> 5, lane = tid & 31;
    int th = (w >= 5) ? 1 : 0;           // sub-tile half
    int u  = (w - 5 * th) * 32 + lane;   // unit in [0,160)
    int rg = u / 10, cg = u % 10;
    int rbl = th * 96 + rg * 6;          // local row base in [0,192)
    int cb  = cg * 10;

    for (int tile = blockIdx.x; tile < ntiles; tile += gridDim.x) {
        int row0 = tile * 192;
        ull acc[6][5];
        #pragma unroll
        for (int i = 0; i < 6; i++)
            #pragma unroll
            for (int j = 0; j < 5; j++) acc[i][j] = 0ull;

        #pragma unroll 1
        for (int kt = 0; kt < 2; kt++) {
            int k0 = kt * 50;
            __syncthreads();
            // coalesced LDG (float2 along k), transposed STS into k-major a_s
            for (int idx = tid; idx < 192 * 25; idx += TPB) {
                int r = idx / 25, k2 = idx - r * 25;
                int gr = row0 + r;
                float2 v = make_float2(0.f, 0.f);
                if (gr < N) v = *(const float2*)(z + (size_t)gr * 100 + k0 + 2 * k2);
                a_s[(2 * k2) * SAR + r]     = v.x;
                a_s[(2 * k2 + 1) * SAR + r] = v.y;
            }
            __syncthreads();

            #pragma unroll 2
            for (int kk = 0; kk < 50; kk++) {
                const float* ar = a_s + kk * SAR + rbl;
                float2 p0 = *(const float2*)ar;
                float2 p1 = *(const float2*)(ar + 2);
                float2 p2 = *(const float2*)(ar + 4);
                const ull* bp = (const ull*)(b_s + (k0 + kk) * 100 + cb);
                ull b2[5];
                #pragma unroll
                for (int j = 0; j < 5; j++) b2[j] = bp[j];
                ull av[6] = { pack2(p0.x, p0.x), pack2(p0.y, p0.y),
                              pack2(p1.x, p1.x), pack2(p1.y, p1.y),
                              pack2(p2.x, p2.x), pack2(p2.y, p2.y) };
                #pragma unroll
                for (int i = 0; i < 6; i++)
                    #pragma unroll
                    for (int j = 0; j < 5; j++) ffma2(acc[i][j], av[i], b2[j]);
            }
        }

        #pragma unroll
        for (int i = 0; i < 6; i++) {
            int gr = row0 + rbl + i;
            if (gr < N) {
                float2* op = (float2*)(out + (size_t)gr * 100 + cb);
                #pragma unroll
                for (int j = 0; j < 5; j++) {
                    float2 r = unpack2(acc[i][j]);
                    r.x += bias_s[cb + 2 * j];
                    r.y += bias_s[cb + 2 * j + 1];
                    op[j] = r;
                }
            }
        }
    }
}

// =================================================================================
// fused edge kernel: e_proj GEMM (attr generated in smem via __cosf) + alpha +
// max-free softmax weight + weighted scatter. BM=192 edges per tile.
// =================================================================================
__global__ void __launch_bounds__(TPB, 2) edge_kernel(
    const float* __restrict__ lu, const float* __restrict__ t,
    const float* __restrict__ msg,
    const float* __restrict__ tw, const float* __restrict__ tb,
    const float* __restrict__ We, const int* __restrict__ ei,
    int E, int ntiles)
{
    extern __shared__ float sm[];
    float* b_s   = sm;                      // [101][100] k-major (We^T)
    float* a_s   = b_s + 10100;             // [51][196] generated attr tile (k-major)
    float* tw_s  = a_s + 51 * SAR;          // [100]
    float* tb_s  = tw_s + 100;              // [100]
    float* rel_s = tb_s + 100;              // [192]
    float* msg_s = rel_s + 192;             // [192]
    float* apart = msg_s + 192;             // [384] alpha partials, then w
    int*   sidx  = (int*)(apart + 384);     // [192]
    int*   didx  = sidx + 192;              // [192]

    int tid = threadIdx.x;
    for (int idx = tid; idx < 10100; idx += TPB) {
        int o = idx / 101, k = idx - o * 101;
        b_s[k * 100 + o] = We[idx];
    }
    if (tid < 100) { tw_s[tid] = tw[tid]; tb_s[tid] = tb[tid]; }

    int w = tid >> 5, lane = tid & 31;
    int th = (w >= 5) ? 1 : 0;
    int u  = (w - 5 * th) * 32 + lane;
    int rg = u / 10, cg = u % 10;
    int rbl = th * 96 + rg * 6;
    int cb  = cg * 10;
    int h   = (cg >= 5) ? 1 : 0;             // head of this colgroup (TN=10 never spans)
    const float inv = 0.14142135623730951f;  // 1/sqrt(50)

    for (int tile = blockIdx.x; tile < ntiles; tile += gridDim.x) {
        int e0 = tile * 192;
        __syncthreads();                     // prev tile fully consumed
        if (tid < 192) {
            int e = e0 + tid; float rv = 0.f, mv = 0.f; int s = 0, d = 0;
            if (e < E) { s = ei[e]; d = ei[E + e]; rv = lu[s] - t[e]; mv = msg[e]; }
            rel_s[tid] = rv; msg_s[tid] = mv; sidx[tid] = s; didx[tid] = d;
        }
        for (int idx = tid; idx < 384; idx += TPB) apart[idx] = 0.f;

        ull acc[6][5];
        #pragma unroll
        for (int i = 0; i < 6; i++)
            #pragma unroll
            for (int j = 0; j < 5; j++) acc[i][j] = 0ull;

        // k-tiles: [0,50) and [50,101); global k==100 row is msg
        #pragma unroll 1
        for (int kt = 0; kt < 2; kt++) {
            int k0 = kt ? 50 : 0;
            int kn = kt ? 51 : 50;
            __syncthreads();
            for (int idx = tid; idx < kn * 192; idx += TPB) {
                int kk = idx / 192, r = idx - kk * 192;
                int gk = k0 + kk;
                a_s[kk * SAR + r] =
                    (gk < 100) ? __cosf(fmaf(rel_s[r], tw_s[gk], tb_s[gk])) : msg_s[r];
            }
            __syncthreads();

            #pragma unroll 2
            for (int kk = 0; kk < kn; kk++) {
                const float* ar = a_s + kk * SAR + rbl;
                float2 p0 = *(const float2*)ar;
                float2 p1 = *(const float2*)(ar + 2);
                float2 p2 = *(const float2*)(ar + 4);
                const ull* bp = (const ull*)(b_s + (k0 + kk) * 100 + cb);
                ull b2[5];
                #pragma unroll
                for (int j = 0; j < 5; j++) b2[j] = bp[j];
                ull av[6] = { pack2(p0.x, p0.x), pack2(p0.y, p0.y),
                              pack2(p1.x, p1.x), pack2(p1.y, p1.y),
                              pack2(p2.x, p2.x), pack2(p2.y, p2.y) };
                #pragma unroll
                for (int i = 0; i < 6; i++)
                    #pragma unroll
                    for (int j = 0; j < 5; j++) ffma2(acc[i][j], av[i], b2[j]);
            }
        }

        // ---- alpha partials: q[dst] . (k[src] + e_proj) over this colgroup ----
        #pragma unroll
        for (int i = 0; i < 6; i++) {
            int r = rbl + i, e = e0 + r;
            if (e < E) {
                int s = sidx[r], d = didx[r];
                const float2* qp = (const float2*)(g_Q + (size_t)d * 100 + cb);
                const float2* kp = (const float2*)(g_K + (size_t)s * 100 + cb);
                float part = 0.f;
                #pragma unroll
                for (int j = 0; j < 5; j++) {
                    float2 ep = unpack2(acc[i][j]);
                    float2 qv = qp[j];
                    float2 kv = kp[j];
                    part = fmaf(qv.x, kv.x + ep.x, part);
                    part = fmaf(qv.y, kv.y + ep.y, part);
                }
                atomicAdd(&apart[2 * r + h], part);
            }
        }
        __syncthreads();

        // ---- w = exp(alpha) (max-free), accumulate denominators ----
        for (int idx = tid; idx < 384; idx += TPB) {
            int r = idx >> 1, hh = idx & 1;
            int e = e0 + r;
            if (e < E) {
                float ww = __expf(apart[idx] * inv);
                apart[idx] = ww;                        // reuse as w_s
                atomicAdd(&g_aden[2 * didx[r] + hh], ww);
            }
        }
        __syncthreads();

        // ---- scatter: AGGW[dst] += (v[src] + e_proj) * w  (vector REDs) ----
        #pragma unroll
        for (int i = 0; i < 6; i++) {
            int r = rbl + i, e = e0 + r;
            if (e < E) {
                int s = sidx[r], d = didx[r];
                const float2* vp = (const float2*)(g_V + (size_t)s * 100 + cb);
                float ww = apart[2 * r + h];
                float m[10];
                #pragma unroll
                for (int j = 0; j < 5; j++) {
                    float2 ep = unpack2(acc[i][j]);
                    float2 vv = vp[j];
                    m[2 * j]     = (vv.x + ep.x) * ww;
                    m[2 * j + 1] = (vv.y + ep.y) * ww;
                }
                float* op = g_AGGW + (size_t)d * 100 + cb;
                if ((cg & 1) == 0) {   // cb % 4 == 0 : 4+4+2
                    atomicAdd((float4*)op,       make_float4(m[0], m[1], m[2], m[3]));
                    atomicAdd((float4*)(op + 4), make_float4(m[4], m[5], m[6], m[7]));
                    atomicAdd((float2*)(op + 8), make_float2(m[8], m[9]));
                } else {               // cb % 4 == 2 : 2+4+4
                    atomicAdd((float2*)op,       make_float2(m[0], m[1]));
                    atomicAdd((float4*)(op + 2), make_float4(m[2], m[3], m[4], m[5]));
                    atomicAdd((float4*)(op + 6), make_float4(m[6], m[7], m[8], m[9]));
                }
            }
        }
    }
}

// =================================================================================
// link predictor with fused normalization:
// z_out = AGG(skip) + AGGW/aden ; out = relu(z_s@Ws^T + z_d@Wd^T + b) @ Wf^T + bf
// =================================================================================
__global__ void __launch_bounds__(128) linkpred_kernel(
    const float* __restrict__ Wsrc, const float* __restrict__ bsrc,
    const float* __restrict__ Wdst, const float* __restrict__ bdst,
    const float* __restrict__ Wf,   const float* __restrict__ bf,
    const int* __restrict__ src, const int* __restrict__ dst,
    float* __restrict__ out, int B)
{
    extern __shared__ float sm[];
    float* Ws   = sm;                 // [100][101] padded
    float* Wd   = Ws + 100 * 101;
    float* bsum = Wd + 100 * 101;
    float* wf   = bsum + 100;
    float* zrow = wf + 100;           // 4 warps * 200

    int tid = threadIdx.x, lane = tid & 31, warp = tid >> 5;
    for (int idx = tid; idx < 10000; idx += 128) {
        int o = idx / 100, k = idx - o * 100;
        Ws[o * 101 + k] = Wsrc[idx];
        Wd[o * 101 + k] = Wdst[idx];
    }
    if (tid < 100) { bsum[tid] = bsrc[tid] + bdst[tid]; wf[tid] = Wf[tid]; }
    __syncthreads();

    float bf0 = bf[0];
    float* zs = zrow + warp * 200;
    float* zd = zs + 100;

    for (int p = blockIdx.x * 4 + warp; p < B; p += gridDim.x * 4) {
        int sp = g_assoc[src[p]];
        int dp = g_assoc[dst[p]];
        float ds0 = g_aden[2 * sp], ds1 = g_aden[2 * sp + 1];
        float dd0 = g_aden[2 * dp], dd1 = g_aden[2 * dp + 1];
        float is0 = ds0 > 0.f ? 1.f / ds0 : 0.f;
        float is1 = ds1 > 0.f ? 1.f / ds1 : 0.f;
        float id0 = dd0 > 0.f ? 1.f / dd0 : 0.f;
        float id1 = dd1 > 0.f ? 1.f / dd1 : 0.f;
        for (int c = lane; c < 100; c += 32) {
            float invs = (c < 50) ? is0 : is1;
            float invd = (c < 50) ? id0 : id1;
            zs[c] = fmaf(g_AGGW[(size_t)sp * 100 + c], invs, g_AGG[(size_t)sp * 100 + c]);
            zd[c] = fmaf(g_AGGW[(size_t)dp * 100 + c], invd, g_AGG[(size_t)dp * 100 + c]);
        }
        __syncwarp();
        float acc = 0.f;
        for (int o = lane; o < 100; o += 32) {
            float hh = bsum[o];
            const float* wsr = Ws + o * 101;
            const float* wdr = Wd + o * 101;
            #pragma unroll 10
            for (int k = 0; k < 100; k++) {
                hh = fmaf(wsr[k], zs[k], hh);
                hh = fmaf(wdr[k], zd[k], hh);
            }
            hh = fmaxf(hh, 0.f);
            acc = fmaf(hh, wf[o], acc);
        }
        #pragma unroll
        for (int o = 16; o; o >>= 1) acc += __shfl_xor_sync(0xffffffffu, acc, o);
        if (lane == 0) out[p] = acc + bf0;
        __syncwarp();
    }
}

// ---------------- launch ----------------------------------------------------------
extern "C" void kernel_launch(void* const* d_in, const int* in_sizes, int n_in,
                              void* d_out, int out_size)
{
    const float* z     = (const float*)d_in[0];
    const float* lu    = (const float*)d_in[1];
    const float* t     = (const float*)d_in[2];
    const float* msg   = (const float*)d_in[3];
    const float* tw    = (const float*)d_in[4];
    const float* tb    = (const float*)d_in[5];
    const float* Wq    = (const float*)d_in[6];
    const float* bq    = (const float*)d_in[7];
    const float* Wk    = (const float*)d_in[8];
    const float* bk    = (const float*)d_in[9];
    const float* Wv    = (const float*)d_in[10];
    const float* bv    = (const float*)d_in[11];
    const float* We    = (const float*)d_in[12];
    const float* Wskip = (const float*)d_in[13];
    const float* bskip = (const float*)d_in[14];
    const float* Wsrc  = (const float*)d_in[15];
    const float* bsrc  = (const float*)d_in[16];
    const float* Wdst  = (const float*)d_in[17];
    const float* bdst  = (const float*)d_in[18];
    const float* Wf    = (const float*)d_in[19];
    const float* bf    = (const float*)d_in[20];
    const int*   n_id  = (const int*)d_in[21];
    const int*   srcp  = (const int*)d_in[22];
    const int*   dstp  = (const int*)d_in[23];
    const int*   ei    = (const int*)d_in[24];

    int N = in_sizes[0] / 100;
    int E = in_sizes[2];
    int B = in_sizes[22];
    float* out = (float*)d_out;

    int ntilesN = (N + 191) / 192;
    int ntilesE = (E + 191) / 192;

    const int SMEM_QKVS = (10000 + 50 * SAR + 100) * 4;                        // ~79.6 KB
    const int SMEM_EDGE = (10100 + 51 * SAR + 100 + 100 + 192 + 192 + 384
                           + 192 + 192) * 4;                                   // ~85.8 KB
    const int SMEM_LP   = (2 * 100 * 101 + 200 + 4 * 200) * 4;                 // ~84.8 KB

    cudaFuncSetAttribute(qkvs_kernel,     cudaFuncAttributeMaxDynamicSharedMemorySize, SMEM_QKVS);
    cudaFuncSetAttribute(edge_kernel,     cudaFuncAttributeMaxDynamicSharedMemorySize, SMEM_EDGE);
    cudaFuncSetAttribute(linkpred_kernel, cudaFuncAttributeMaxDynamicSharedMemorySize, SMEM_LP);

    init_kernel<<<(N * 25 + 255) / 256, 256>>>(N);
    assoc_kernel<<<(N + 255) / 256, 256>>>(n_id, N);

    dim3 gq(74, 4);    // 296 persistent CTAs (148 SMs x 2), 4 weight sets
    qkvs_kernel<<<gq, TPB, SMEM_QKVS>>>(z, Wq, bq, Wk, bk, Wv, bv, Wskip, bskip,
                                        N, ntilesN);

    edge_kernel<<<296, TPB, SMEM_EDGE>>>(lu, t, msg, tw, tb, We, ei, E, ntilesE);

    linkpred_kernel<<<296, 128, SMEM_LP>>>(Wsrc, bsrc, Wdst, bdst, Wf, bf,
                                           srcp, dstp, out, B);
}